// round 1
// baseline (speedup 1.0000x reference)
#include <cuda_runtime.h>

#define Bb 2
#define Nn 8192
#define Ff 64
#define Oo 64

// Scratch (allocation-free rule: __device__ globals)
__device__ float g_si[Bb * Nn];
__device__ float g_sj[Bb * Nn];
__device__ float g_Sj[Bb];
__device__ float g_u[Bb * Ff];
__device__ float g_v[Bb * Ff];
__device__ float g_P[Bb * Oo];
__device__ float g_Q[Bb * Oo];

// ---------------------------------------------------------------------------
// Pass 0: zero the atomic accumulators (must happen every call; graph-replayed)
// ---------------------------------------------------------------------------
__global__ void k_init() {
    int t = threadIdx.x;           // 128 threads
    if (t < Bb) g_Sj[t] = 0.0f;
    g_u[t] = 0.0f;                 // Bb*Ff = 128
    g_v[t] = 0.0f;
}

// ---------------------------------------------------------------------------
// Pass A: si[b,n] = x[b,n,:]·w_i , sj[b,n] = x[b,n,:]·w_j , Sj[b] = sum sj
// 16 lanes per row (float4 each), shfl-segment reduce. 1024 blocks x 256.
// ---------------------------------------------------------------------------
__global__ void k_passA(const float* __restrict__ x,
                        const float* __restrict__ adj_w) {
    int gid  = blockIdx.x * blockDim.x + threadIdx.x;
    int row  = gid >> 4;           // global row in [0, Bb*Nn)
    int lane = gid & 15;

    float4 xv = reinterpret_cast<const float4*>(x)[row * 16 + lane];
    float4 wj = reinterpret_cast<const float4*>(adj_w)[lane];        // adj_w[:F]
    float4 wi = reinterpret_cast<const float4*>(adj_w)[16 + lane];   // adj_w[F:]

    float pj = xv.x * wj.x + xv.y * wj.y + xv.z * wj.z + xv.w * wj.w;
    float pi = xv.x * wi.x + xv.y * wi.y + xv.z * wi.z + xv.w * wi.w;

    #pragma unroll
    for (int off = 8; off > 0; off >>= 1) {
        pj += __shfl_down_sync(0xffffffffu, pj, off, 16);
        pi += __shfl_down_sync(0xffffffffu, pi, off, 16);
    }

    __shared__ float s_sum;
    if (threadIdx.x == 0) s_sum = 0.0f;
    __syncthreads();
    if (lane == 0) {
        g_si[row] = pi;
        g_sj[row] = pj;
        atomicAdd(&s_sum, pj);
    }
    __syncthreads();
    if (threadIdx.x == 0) {
        // 16 rows per block, batch boundary is block-aligned -> single batch/block
        atomicAdd(&g_Sj[row / Nn], s_sum);
    }
}

// ---------------------------------------------------------------------------
// Pass B: u[b,f] = sum_j d[j]*x[j,f] ; v[b,f] = sum_j sj[j]*d[j]*x[j,f]
// d[j] recomputed analytically: rsqrt(max(N*(si+c)+Sj, 1)).
// 32 blocks per batch x 256 threads; register accumulate -> shared -> global.
// ---------------------------------------------------------------------------
__global__ void k_passB(const float* __restrict__ x,
                        const float* __restrict__ adj_b) {
    __shared__ float s_u[Ff], s_v[Ff];
    int b    = blockIdx.x >> 5;
    int blk  = blockIdx.x & 31;
    int grp  = threadIdx.x >> 4;   // 0..15 (row group)
    int lane = threadIdx.x & 15;   // feature quad

    if (threadIdx.x < Ff) { s_u[threadIdx.x] = 0.0f; s_v[threadIdx.x] = 0.0f; }
    __syncthreads();

    float c  = adj_b[0];
    float Sj = g_Sj[b];

    float4 au = make_float4(0.f, 0.f, 0.f, 0.f);
    float4 av = make_float4(0.f, 0.f, 0.f, 0.f);

    int base = blk * 256 + grp;    // 256 rows per block
    #pragma unroll 4
    for (int it = 0; it < 16; ++it) {
        int row = b * Nn + base + it * 16;
        float si = g_si[row];
        float sj = g_sj[row];
        float rs = (float)Nn * (si + c) + Sj;
        float d  = rsqrtf(fmaxf(rs, 1.0f));
        float sd = sj * d;
        float4 xv = reinterpret_cast<const float4*>(x)[row * 16 + lane];
        au.x += d * xv.x;  au.y += d * xv.y;  au.z += d * xv.z;  au.w += d * xv.w;
        av.x += sd * xv.x; av.y += sd * xv.y; av.z += sd * xv.z; av.w += sd * xv.w;
    }

    atomicAdd(&s_u[lane * 4 + 0], au.x);
    atomicAdd(&s_u[lane * 4 + 1], au.y);
    atomicAdd(&s_u[lane * 4 + 2], au.z);
    atomicAdd(&s_u[lane * 4 + 3], au.w);
    atomicAdd(&s_v[lane * 4 + 0], av.x);
    atomicAdd(&s_v[lane * 4 + 1], av.y);
    atomicAdd(&s_v[lane * 4 + 2], av.z);
    atomicAdd(&s_v[lane * 4 + 3], av.w);
    __syncthreads();

    if (threadIdx.x < Ff) {
        atomicAdd(&g_u[b * Ff + threadIdx.x], s_u[threadIdx.x]);
        atomicAdd(&g_v[b * Ff + threadIdx.x], s_v[threadIdx.x]);
    }
}

// ---------------------------------------------------------------------------
// Pass C: P[b,:] = u[b,:] @ W ; Q[b,:] = v[b,:] @ W   (64x64 micro-GEMM)
// ---------------------------------------------------------------------------
__global__ void k_passC(const float* __restrict__ weight) {
    int t = threadIdx.x;           // 128 = Bb*Oo
    int b = t >> 6, o = t & 63;
    float p = 0.0f, q = 0.0f;
    #pragma unroll
    for (int f = 0; f < Ff; ++f) {
        float w = weight[f * Oo + o];
        p += g_u[b * Ff + f] * w;
        q += g_v[b * Ff + f] * w;
    }
    g_P[t] = p;
    g_Q[t] = q;
}

// ---------------------------------------------------------------------------
// Pass D: out[b,i,o] = relu( d[i]*((si[i]+c)*P[o] + Q[o]) + bias[o] )
// float4 stores, 1024 blocks x 256 threads.
// ---------------------------------------------------------------------------
__global__ void k_passD(const float* __restrict__ adj_b,
                        const float* __restrict__ bias,
                        float* __restrict__ out) {
    __shared__ float sP[Oo], sQ[Oo], sB[Oo];
    int gid  = blockIdx.x * blockDim.x + threadIdx.x;
    int row  = gid >> 4;
    int lane = gid & 15;
    int b    = row / Nn;           // single batch per block (block-aligned)

    if (threadIdx.x < Oo) {
        sP[threadIdx.x] = g_P[b * Oo + threadIdx.x];
        sQ[threadIdx.x] = g_Q[b * Oo + threadIdx.x];
        sB[threadIdx.x] = bias[threadIdx.x];
    }
    __syncthreads();

    float c  = adj_b[0];
    float si = g_si[row];
    float rs = (float)Nn * (si + c) + g_Sj[b];
    float d  = rsqrtf(fmaxf(rs, 1.0f));
    float a  = si + c;

    int o = lane * 4;
    float4 r;
    r.x = fmaxf(d * (a * sP[o + 0] + sQ[o + 0]) + sB[o + 0], 0.0f);
    r.y = fmaxf(d * (a * sP[o + 1] + sQ[o + 1]) + sB[o + 1], 0.0f);
    r.z = fmaxf(d * (a * sP[o + 2] + sQ[o + 2]) + sB[o + 2], 0.0f);
    r.w = fmaxf(d * (a * sP[o + 3] + sQ[o + 3]) + sB[o + 3], 0.0f);
    reinterpret_cast<float4*>(out)[row * 16 + lane] = r;
}

// ---------------------------------------------------------------------------
extern "C" void kernel_launch(void* const* d_in, const int* in_sizes, int n_in,
                              void* d_out, int out_size) {
    const float* x      = (const float*)d_in[0];   // (2, 8192, 64)
    const float* adj_w  = (const float*)d_in[1];   // (128,)
    const float* adj_b  = (const float*)d_in[2];   // (1,)
    const float* weight = (const float*)d_in[3];   // (64, 64)
    const float* bias   = (const float*)d_in[4];   // (64,)
    float* out = (float*)d_out;                    // (2, 8192, 64)

    k_init <<<1, 128>>>();
    k_passA<<<(Bb * Nn) / 16, 256>>>(x, adj_w);
    k_passB<<<Bb * 32, 256>>>(x, adj_b);
    k_passC<<<1, 128>>>(weight);
    k_passD<<<(Bb * Nn) / 16, 256>>>(adj_b, bias, out);
}

// round 2
// speedup vs baseline: 1.4125x; 1.4125x over previous
#include <cuda_runtime.h>

#define Bb 2
#define Nn 8192
#define Ff 64
#define Oo 64
#define GRID 128
#define TPB 256
#define RPB 128          // rows per block (16384 / 128)
#define ITERS 8          // RPB / 16 row-groups

// Scratch (allocation-free rule: __device__ globals).
// All plain-store written each launch before being read -> no init pass needed.
__device__ float g_part_Sj[GRID];
__device__ float g_part_u[GRID * Ff];
__device__ float g_part_v[GRID * Ff];
// Monotone grid-barrier counter. NEVER reset: each launch consumes exactly
// 2*GRID increments; epoch E = token/(2*GRID) recovers per-launch targets.
__device__ unsigned long long g_ctr;

__device__ __forceinline__ void grid_barrier(unsigned int phase) {
    __syncthreads();
    if (threadIdx.x == 0) {
        __threadfence();
        unsigned long long token = atomicAdd(&g_ctr, 1ULL);
        const unsigned long long G = (unsigned long long)GRID;
        unsigned long long E = token / (2ULL * G);
        unsigned long long target = E * 2ULL * G + (unsigned long long)phase * G;
        unsigned long long v;
        for (;;) {
            asm volatile("ld.global.acquire.gpu.u64 %0, [%1];"
                         : "=l"(v) : "l"(&g_ctr) : "memory");
            if (v >= target) break;
            __nanosleep(32);
        }
    }
    __syncthreads();
}

__global__ void __launch_bounds__(TPB, 1) k_fused(
    const float* __restrict__ x, const float* __restrict__ adj_w,
    const float* __restrict__ adj_b, const float* __restrict__ weight,
    const float* __restrict__ bias, float* __restrict__ out)
{
    __shared__ float s_si[RPB], s_sj[RPB];
    __shared__ float s_pu[16 * Ff];   // per-row-group u partials
    __shared__ float s_pv[16 * Ff];   // per-row-group v partials
    __shared__ float s_u[Ff], s_v[Ff];
    __shared__ float sP[Oo], sQ[Oo], sB[Oo];
    __shared__ float s_blkSj, s_Sj;

    const int tid  = threadIdx.x;
    const int lane = tid & 15;        // feature quad index (0..15)
    const int grp  = tid >> 4;        // row group (0..15)
    const int bid  = blockIdx.x;
    const int bb   = bid >> 6;        // batch (64 blocks per batch)
    const int row0 = bid * RPB;

    const float c = adj_b[0];
    if (tid == 0) s_blkSj = 0.0f;

    // ---------------- Phase 1: si/sj per row, block Sj partial --------------
    // x rows held in registers for the whole kernel: DRAM reads x exactly once.
    float4 xv[ITERS];
    #pragma unroll
    for (int it = 0; it < ITERS; ++it)
        xv[it] = reinterpret_cast<const float4*>(x)[(row0 + it * 16 + grp) * 16 + lane];

    const float4 wj = reinterpret_cast<const float4*>(adj_w)[lane];        // adj_w[:F]
    const float4 wi = reinterpret_cast<const float4*>(adj_w)[16 + lane];   // adj_w[F:]

    float bsum = 0.0f;
    #pragma unroll
    for (int it = 0; it < ITERS; ++it) {
        float pj = xv[it].x * wj.x + xv[it].y * wj.y + xv[it].z * wj.z + xv[it].w * wj.w;
        float pi = xv[it].x * wi.x + xv[it].y * wi.y + xv[it].z * wi.z + xv[it].w * wi.w;
        #pragma unroll
        for (int off = 8; off; off >>= 1) {
            pj += __shfl_down_sync(0xffffffffu, pj, off, 16);
            pi += __shfl_down_sync(0xffffffffu, pi, off, 16);
        }
        if (lane == 0) {
            s_si[it * 16 + grp] = pi;
            s_sj[it * 16 + grp] = pj;
            bsum += pj;
        }
    }
    __syncthreads();
    if (lane == 0) atomicAdd(&s_blkSj, bsum);   // 16 adds, one-time
    __syncthreads();
    if (tid == 0) g_part_Sj[bid] = s_blkSj;

    grid_barrier(1);

    // ---------------- Sj reduce for my batch --------------------------------
    if (tid == 0) s_Sj = 0.0f;
    __syncthreads();
    if (tid < 64) atomicAdd(&s_Sj, __ldcg(&g_part_Sj[bb * 64 + tid]));
    __syncthreads();
    const float Sj = s_Sj;

    // ---------------- Phase 2: u/v block partials ---------------------------
    float4 au = make_float4(0.f, 0.f, 0.f, 0.f);
    float4 av = make_float4(0.f, 0.f, 0.f, 0.f);
    #pragma unroll
    for (int it = 0; it < ITERS; ++it) {
        int lr = it * 16 + grp;
        float si = s_si[lr], sj = s_sj[lr];
        float d  = rsqrtf(fmaxf((float)Nn * (si + c) + Sj, 1.0f));
        float sd = sj * d;
        au.x += d  * xv[it].x;  au.y += d  * xv[it].y;
        au.z += d  * xv[it].z;  au.w += d  * xv[it].w;
        av.x += sd * xv[it].x;  av.y += sd * xv[it].y;
        av.z += sd * xv[it].z;  av.w += sd * xv[it].w;
    }
    s_pu[grp * Ff + lane * 4 + 0] = au.x;
    s_pu[grp * Ff + lane * 4 + 1] = au.y;
    s_pu[grp * Ff + lane * 4 + 2] = au.z;
    s_pu[grp * Ff + lane * 4 + 3] = au.w;
    s_pv[grp * Ff + lane * 4 + 0] = av.x;
    s_pv[grp * Ff + lane * 4 + 1] = av.y;
    s_pv[grp * Ff + lane * 4 + 2] = av.z;
    s_pv[grp * Ff + lane * 4 + 3] = av.w;
    __syncthreads();
    if (tid < 64) {
        float a = 0.f;
        #pragma unroll
        for (int g = 0; g < 16; ++g) a += s_pu[g * Ff + tid];
        g_part_u[bid * Ff + tid] = a;
    } else if (tid < 128) {
        int f = tid - 64;
        float a = 0.f;
        #pragma unroll
        for (int g = 0; g < 16; ++g) a += s_pv[g * Ff + f];
        g_part_v[bid * Ff + f] = a;
    }

    grid_barrier(2);

    // ---------------- Phase 3: reduce u/v, micro-GEMM P/Q (per block) -------
    if (tid < 64) {
        float acc = 0.f;
        #pragma unroll 8
        for (int k = 0; k < 64; ++k)
            acc += __ldcg(&g_part_u[(bb * 64 + k) * Ff + tid]);
        s_u[tid] = acc;
    } else if (tid < 128) {
        int f = tid - 64;
        float acc = 0.f;
        #pragma unroll 8
        for (int k = 0; k < 64; ++k)
            acc += __ldcg(&g_part_v[(bb * 64 + k) * Ff + f]);
        s_v[f] = acc;
    } else if (tid < 192) {
        sB[tid - 128] = bias[tid - 128];
    }
    __syncthreads();
    if (tid < 64) {
        float p = 0.f;
        #pragma unroll
        for (int f = 0; f < Ff; ++f) p = fmaf(s_u[f], __ldg(&weight[f * Oo + tid]), p);
        sP[tid] = p;
    } else if (tid < 128) {
        int o = tid - 64;
        float q = 0.f;
        #pragma unroll
        for (int f = 0; f < Ff; ++f) q = fmaf(s_v[f], __ldg(&weight[f * Oo + o]), q);
        sQ[o] = q;
    }
    __syncthreads();

    // ---------------- Phase 4: rank-1 epilogue ------------------------------
    const int o4 = lane * 4;
    const float P0 = sP[o4 + 0], P1 = sP[o4 + 1], P2 = sP[o4 + 2], P3 = sP[o4 + 3];
    const float Q0 = sQ[o4 + 0], Q1 = sQ[o4 + 1], Q2 = sQ[o4 + 2], Q3 = sQ[o4 + 3];
    const float B0 = sB[o4 + 0], B1 = sB[o4 + 1], B2 = sB[o4 + 2], B3 = sB[o4 + 3];
    #pragma unroll
    for (int it = 0; it < ITERS; ++it) {
        int lr = it * 16 + grp;
        float si = s_si[lr];
        float d  = rsqrtf(fmaxf((float)Nn * (si + c) + Sj, 1.0f));
        float a  = si + c;
        float4 r;
        r.x = fmaxf(fmaf(d, fmaf(a, P0, Q0), B0), 0.0f);
        r.y = fmaxf(fmaf(d, fmaf(a, P1, Q1), B1), 0.0f);
        r.z = fmaxf(fmaf(d, fmaf(a, P2, Q2), B2), 0.0f);
        r.w = fmaxf(fmaf(d, fmaf(a, P3, Q3), B3), 0.0f);
        reinterpret_cast<float4*>(out)[(row0 + lr) * 16 + lane] = r;
    }
}

extern "C" void kernel_launch(void* const* d_in, const int* in_sizes, int n_in,
                              void* d_out, int out_size) {
    const float* x      = (const float*)d_in[0];   // (2, 8192, 64)
    const float* adj_w  = (const float*)d_in[1];   // (128,)
    const float* adj_b  = (const float*)d_in[2];   // (1,)
    const float* weight = (const float*)d_in[3];   // (64, 64)
    const float* bias   = (const float*)d_in[4];   // (64,)
    float* out = (float*)d_out;                    // (2, 8192, 64)

    k_fused<<<GRID, TPB>>>(x, adj_w, adj_b, weight, bias, out);
}